// round 6
// baseline (speedup 1.0000x reference)
#include <cuda_runtime.h>
#include <cstdint>
#include <cstddef>

#define NPTS 80000
#define H    32
#define KPTS 15
#define CIN  128
#define COUT 256
#define D2   64
#define INFL 0.4f
#define EPS  1e-5f
#define SLOPE 0.2f

typedef unsigned long long ull;

// ---------------- device scratch ----------------
__device__ __align__(128) float g_x1 [(size_t)NPTS * D2];           // unary_1 out
__device__ __align__(128) float g_fk [(size_t)NPTS * KPTS * D2];    // [n][k*64+d]
__device__ __align__(128) float g_xkp[(size_t)NPTS * D2];           // KPConv out
__device__ __align__(128) float g_y2 [(size_t)NPTS * COUT];         // unary_2 pre-BN
__device__ __align__(128) float g_part[256 * 2 * COUT];
__device__ __align__(128) float g_bn1 [2 * D2];
__device__ __align__(128) float g_bn2 [2 * COUT];
__device__ __align__(128) float g_bnsc[2 * COUT];

__device__ __forceinline__ float leaky(float v) { return v > 0.f ? v : v * SLOPE; }

// ---------------- packed f32x2 helpers ----------------
__device__ __forceinline__ ull pack2(float a, float b) {
    ull p;
    asm("mov.b64 %0, {%1, %2};" : "=l"(p) : "f"(a), "f"(b));
    return p;
}
__device__ __forceinline__ void unpack2(ull p, float& a, float& b) {
    asm("mov.b64 {%0, %1}, %2;" : "=f"(a), "=f"(b) : "l"(p));
}
__device__ __forceinline__ void ffma2(ull& acc, ull a, ull b) {
    asm("fma.rn.f32x2 %0, %1, %2, %0;" : "+l"(acc) : "l"(a), "l"(b));
}

// ---------------- f32x2 register-tiled GEMM ----------------
// C[M x ND] = A[M x KD] @ B[KD x ND], row-major. Block tile 128x64,
// 256 threads, thread tile 8 rows x 4 cols (2 f32x2 col-pairs).
// A is staged in smem DUPLICATED: sAd[k][r] = (a, a) as 64-bit, so the
// inner loop has no packing movs: 5 LDS.128 + 16 FFMA2 per k.
template<int KD, int ND>
__global__ __launch_bounds__(256)
void gemm_f2(const float* __restrict__ A, const float* __restrict__ B,
             float* __restrict__ C) {
    __shared__ ull   sAd[32][128];   // [k][r] duplicated pairs (32 KB)
    __shared__ float sB [32][64];    // [k][c] (8 KB)

    const int tid  = threadIdx.x;
    const int ty   = tid >> 4;       // 0..15 -> row group
    const int tx   = tid & 15;       // 0..15 -> col group
    const int rr   = ty * 8;
    const int cc   = tx * 4;
    const int row0 = blockIdx.x * 128;
    const int col0 = blockIdx.y * 64;

    ull acc[8][2];
#pragma unroll
    for (int i = 0; i < 8; i++) { acc[i][0] = 0ull; acc[i][1] = 0ull; }

    for (int k0 = 0; k0 < KD; k0 += 32) {
        // ---- stage tiles ----
        // A: 128 rows x 32 k = 1024 float4 chunks, 4 per thread
        float4 va[4];
#pragma unroll
        for (int i = 0; i < 4; i++) {
            const int id = tid + i * 256;
            const int r  = id >> 3;
            const int c4 = (id & 7) * 4;
            va[i] = *(const float4*)&A[(size_t)(row0 + r) * KD + k0 + c4];
        }
        // B: 32 k x 64 c = 512 float4 chunks, 2 per thread
        float4 vb[2];
#pragma unroll
        for (int i = 0; i < 2; i++) {
            const int id = tid + i * 256;
            const int r  = id >> 4;
            const int c4 = (id & 15) * 4;
            vb[i] = *(const float4*)&B[(size_t)(k0 + r) * ND + col0 + c4];
        }
        __syncthreads();   // previous iter reads done
#pragma unroll
        for (int i = 0; i < 4; i++) {
            const int id = tid + i * 256;
            const int r  = id >> 3;
            const int c4 = (id & 7) * 4;
            sAd[c4 + 0][r] = pack2(va[i].x, va[i].x);
            sAd[c4 + 1][r] = pack2(va[i].y, va[i].y);
            sAd[c4 + 2][r] = pack2(va[i].z, va[i].z);
            sAd[c4 + 3][r] = pack2(va[i].w, va[i].w);
        }
#pragma unroll
        for (int i = 0; i < 2; i++) {
            const int id = tid + i * 256;
            const int r  = id >> 4;
            const int c4 = (id & 15) * 4;
            *(float4*)&sB[r][c4] = vb[i];
        }
        __syncthreads();

        // ---- compute ----
#pragma unroll
        for (int kk = 0; kk < 32; kk++) {
            const ulonglong2 b2 = *(const ulonglong2*)&sB[kk][cc];  // (b0,b1),(b2,b3)
            const ulonglong2 a0 = *(const ulonglong2*)&sAd[kk][rr + 0];
            const ulonglong2 a1 = *(const ulonglong2*)&sAd[kk][rr + 2];
            const ulonglong2 a2 = *(const ulonglong2*)&sAd[kk][rr + 4];
            const ulonglong2 a3 = *(const ulonglong2*)&sAd[kk][rr + 6];
            ffma2(acc[0][0], a0.x, b2.x); ffma2(acc[0][1], a0.x, b2.y);
            ffma2(acc[1][0], a0.y, b2.x); ffma2(acc[1][1], a0.y, b2.y);
            ffma2(acc[2][0], a1.x, b2.x); ffma2(acc[2][1], a1.x, b2.y);
            ffma2(acc[3][0], a1.y, b2.x); ffma2(acc[3][1], a1.y, b2.y);
            ffma2(acc[4][0], a2.x, b2.x); ffma2(acc[4][1], a2.x, b2.y);
            ffma2(acc[5][0], a2.y, b2.x); ffma2(acc[5][1], a2.y, b2.y);
            ffma2(acc[6][0], a3.x, b2.x); ffma2(acc[6][1], a3.x, b2.y);
            ffma2(acc[7][0], a3.y, b2.x); ffma2(acc[7][1], a3.y, b2.y);
        }
        __syncthreads();
    }

#pragma unroll
    for (int i = 0; i < 8; i++) {
        float c0, c1, c2, c3;
        unpack2(acc[i][0], c0, c1);
        unpack2(acc[i][1], c2, c3);
        *(float4*)&C[(size_t)(row0 + rr + i) * ND + col0 + cc] =
            make_float4(c0, c1, c2, c3);
    }
}

// ---------------- column stats (deterministic 2-stage) ----------------
template<int C>
__global__ __launch_bounds__(256)
void colstats(const float* __restrict__ y, float* __restrict__ part) {
    const int tid = threadIdx.x, bid = blockIdx.x;
    if (C == 256) {
        float s = 0.f, q = 0.f;
        for (int r = bid; r < NPTS; r += 256) {
            float v = y[(size_t)r * 256 + tid];
            s += v; q += v * v;
        }
        part[bid * 512 + tid] = s;
        part[bid * 512 + 256 + tid] = q;
    } else {
        const int c = tid & 63, rg = tid >> 6;
        float s = 0.f, q = 0.f;
        for (int r = bid * 4 + rg; r < NPTS; r += 1024) {
            float v = y[(size_t)r * 64 + c];
            s += v; q += v * v;
        }
        __shared__ float sh[2][256];
        sh[0][tid] = s; sh[1][tid] = q;
        __syncthreads();
        if (tid < 64) {
            s = sh[0][tid] + sh[0][tid + 64] + sh[0][tid + 128] + sh[0][tid + 192];
            q = sh[1][tid] + sh[1][tid + 64] + sh[1][tid + 128] + sh[1][tid + 192];
            part[bid * 128 + tid] = s;
            part[bid * 128 + 64 + tid] = q;
        }
    }
}

template<int C>
__global__ void finalize_bn(const float* __restrict__ part,
                            const float* __restrict__ g, const float* __restrict__ b,
                            float* __restrict__ bnout) {
    const int c = threadIdx.x;
    float s = 0.f, q = 0.f;
    for (int i = 0; i < 256; i++) {
        s += part[i * 2 * C + c];
        q += part[i * 2 * C + C + c];
    }
    const float mean = s / (float)NPTS;
    const float var = q / (float)NPTS - mean * mean;
    const float sc = g[c] * rsqrtf(var + EPS);
    bnout[c] = sc;
    bnout[C + c] = b[c] - mean * sc;
}

// ---------------- BN1 apply + leaky relu (in place) ----------------
__global__ __launch_bounds__(256)
void bn_act_64(float* __restrict__ x, const float* __restrict__ bn) {
    const size_t i = (size_t)blockIdx.x * 256 + threadIdx.x;
    float4 v = ((float4*)x)[i];
    const int c = (int)((i * 4) & 63);
    v.x = leaky(v.x * bn[c + 0] + bn[64 + c + 0]);
    v.y = leaky(v.y * bn[c + 1] + bn[64 + c + 1]);
    v.z = leaky(v.z * bn[c + 2] + bn[64 + c + 2]);
    v.w = leaky(v.w * bn[c + 3] + bn[64 + c + 3]);
    ((float4*)x)[i] = v;
}

// ---------------- KPConv: influence weights + fk accumulation ----------------
__global__ __launch_bounds__(256)
void kpconv_kernel(const float* __restrict__ xyz, const int* __restrict__ nbr,
                   const float* __restrict__ kp) {
    __shared__ float s_kp[KPTS * 3];
    __shared__ int   s_nbr[16][H];
    __shared__ float s_w[16 * 481];

    const int tid = threadIdx.x;
    const int n0 = blockIdx.x * 16;

    if (tid < KPTS * 3) s_kp[tid] = kp[tid];
    __syncthreads();

    for (int t = tid; t < 512; t += 256) {
        const int p = t >> 5, h = t & 31;
        const int n = n0 + p;
        const int j = nbr[n * H + h];
        s_nbr[p][h] = j;
        const float dx = xyz[j * 3 + 0] - xyz[n * 3 + 0];
        const float dy = xyz[j * 3 + 1] - xyz[n * 3 + 1];
        const float dz = xyz[j * 3 + 2] - xyz[n * 3 + 2];
        float* wp = &s_w[p * 481 + h * 15];
#pragma unroll
        for (int k = 0; k < KPTS; k++) {
            const float ex = dx - s_kp[k * 3 + 0];
            const float ey = dy - s_kp[k * 3 + 1];
            const float ez = dz - s_kp[k * 3 + 2];
            const float sq = ex * ex + ey * ey + ez * ez;
            wp[k] = fmaxf(1.f - sqrtf(sq) * (1.f / INFL), 0.f);
        }
    }
    __syncthreads();

    const int p = tid >> 4;
    const int d0 = (tid & 15) * 4;
    const int n = n0 + p;
    ull acc0[KPTS], acc1[KPTS];
#pragma unroll
    for (int k = 0; k < KPTS; k++) { acc0[k] = 0ull; acc1[k] = 0ull; }
    const float* wrow = &s_w[p * 481];
    for (int h = 0; h < H; h++) {
        const int j = s_nbr[p][h];
        const float4 v = *(const float4*)&g_x1[(size_t)j * 64 + d0];
        const ull v01 = pack2(v.x, v.y);
        const ull v23 = pack2(v.z, v.w);
        const float* wp = wrow + h * 15;
#pragma unroll
        for (int k = 0; k < KPTS; k++) {
            const float w = wp[k];
            const ull w2 = pack2(w, w);
            ffma2(acc0[k], w2, v01);
            ffma2(acc1[k], w2, v23);
        }
    }
    float* dst = &g_fk[(size_t)n * (KPTS * 64) + d0];
#pragma unroll
    for (int k = 0; k < KPTS; k++) {
        float a0, a1, a2, a3;
        unpack2(acc0[k], a0, a1);
        unpack2(acc1[k], a2, a3);
        *(float4*)&dst[k * 64] = make_float4(a0, a1, a2, a3);
    }
}

// ---------------- final combine ----------------
__global__ __launch_bounds__(256)
void combine_kernel(const float* __restrict__ y2, float* __restrict__ out,
                    const float* __restrict__ bn2, const float* __restrict__ bnsc) {
    const size_t i = (size_t)blockIdx.x * 256 + threadIdx.x;
    const int c = (int)((i * 4) & 255);
    float4 a = ((const float4*)y2)[i];
    float4 s = ((float4*)out)[i];
    float4 r;
    r.x = leaky(a.x * bn2[c + 0] + bn2[256 + c + 0]) + (s.x * bnsc[c + 0] + bnsc[256 + c + 0]);
    r.y = leaky(a.y * bn2[c + 1] + bn2[256 + c + 1]) + (s.y * bnsc[c + 1] + bnsc[256 + c + 1]);
    r.z = leaky(a.z * bn2[c + 2] + bn2[256 + c + 2]) + (s.z * bnsc[c + 2] + bnsc[256 + c + 2]);
    r.w = leaky(a.w * bn2[c + 3] + bn2[256 + c + 3]) + (s.w * bnsc[c + 3] + bnsc[256 + c + 3]);
    ((float4*)out)[i] = r;
}

// ---------------- launcher ----------------
extern "C" void kernel_launch(void* const* d_in, const int* in_sizes, int n_in,
                              void* d_out, int out_size) {
    const float* feats = (const float*)d_in[0];
    const float* xyz   = (const float*)d_in[1];
    const int*   nbr   = (const int*)d_in[3];
    const float* W1    = (const float*)d_in[4];
    const float* g1    = (const float*)d_in[5];
    const float* b1    = (const float*)d_in[6];
    const float* kpp   = (const float*)d_in[7];
    const float* kpw   = (const float*)d_in[8];   // [15*64][64] natural layout
    const float* W2    = (const float*)d_in[9];
    const float* g2    = (const float*)d_in[10];
    const float* b2    = (const float*)d_in[11];
    const float* Wsc   = (const float*)d_in[12];
    const float* gsc   = (const float*)d_in[13];
    const float* bsc   = (const float*)d_in[14];
    float* out = (float*)d_out;

    void *px1, *pfk, *pxkp, *py2, *ppart, *pbn1, *pbn2, *pbnsc;
    cudaGetSymbolAddress(&px1, g_x1);
    cudaGetSymbolAddress(&pfk, g_fk);
    cudaGetSymbolAddress(&pxkp, g_xkp);
    cudaGetSymbolAddress(&py2, g_y2);
    cudaGetSymbolAddress(&ppart, g_part);
    cudaGetSymbolAddress(&pbn1, g_bn1);
    cudaGetSymbolAddress(&pbn2, g_bn2);
    cudaGetSymbolAddress(&pbnsc, g_bnsc);
    float *x1 = (float*)px1, *fk = (float*)pfk, *xkp = (float*)pxkp;
    float *y2 = (float*)py2, *part = (float*)ppart;
    float *bn1 = (float*)pbn1, *bn2 = (float*)pbn2, *bnsc = (float*)pbnsc;

    // 1) unary_1: x1 = feats @ W1  [N,64]
    gemm_f2<128, 64><<<dim3(625, 1), 256>>>(feats, W1, x1);
    // 2) BN1 + act
    colstats<64><<<256, 256>>>(x1, part);
    finalize_bn<64><<<1, 64>>>(part, g1, b1, bn1);
    bn_act_64<<<NPTS * 64 / 4 / 256, 256>>>(x1, bn1);
    // 3) KPConv -> fk [N, 960]
    kpconv_kernel<<<NPTS / 16, 256>>>(xyz, nbr, kpp);
    // 4) x_kp = fk @ kp_weights  [N,960]@[960,64]
    gemm_f2<960, 64><<<dim3(625, 1), 256>>>(fk, kpw, xkp);
    // 5) y2 = x_kp @ W2  [N,256]
    gemm_f2<64, 256><<<dim3(625, 4), 256>>>(xkp, W2, y2);
    colstats<256><<<256, 256>>>(y2, part);
    finalize_bn<256><<<1, 256>>>(part, g2, b2, bn2);
    // 6) shortcut -> out raw
    gemm_f2<128, 256><<<dim3(625, 4), 256>>>(feats, Wsc, out);
    colstats<256><<<256, 256>>>(out, part);
    finalize_bn<256><<<1, 256>>>(part, gsc, bsc, bnsc);
    // 7) combine
    combine_kernel<<<NPTS * 256 / 4 / 256, 256>>>(y2, out, bn2, bnsc);
}

// round 9
// speedup vs baseline: 1.4289x; 1.4289x over previous
#include <cuda_runtime.h>
#include <cstdint>
#include <cstddef>

#define NPTS 80000
#define H    32
#define KPTS 15
#define CIN  128
#define COUT 256
#define D2   64
#define INFL 0.4f
#define EPS  1e-5f
#define SLOPE 0.2f

// ---------------- device scratch ----------------
__device__ __align__(128) float g_x1 [(size_t)NPTS * D2];           // unary_1 out
__device__ __align__(128) float g_fk [(size_t)NPTS * KPTS * D2];    // [n][k*64+d]
__device__ __align__(128) float g_xkp[(size_t)NPTS * D2];           // KPConv out
__device__ __align__(128) float g_y2 [(size_t)NPTS * COUT];         // unary_2 pre-BN
__device__ __align__(128) float g_part[256 * 2 * COUT];
__device__ __align__(128) float g_bn1 [2 * D2];
__device__ __align__(128) float g_bn2 [2 * COUT];
__device__ __align__(128) float g_bnsc[2 * COUT];

__device__ __forceinline__ float leaky(float v) { return v > 0.f ? v : v * SLOPE; }

// ---------------- double-buffered fp32 GEMM ----------------
// C[M x ND] = A[M x KD] @ B[KD x ND], row-major. Block tile 64x64,
// 128 threads, thread tile 8 rows x 4 cols: per k, 3 LDS.128 + 32 FFMA.
template<int KD, int ND>
__global__ __launch_bounds__(128, 6)
void gemm_k(const float* __restrict__ A, const float* __restrict__ B,
            float* __restrict__ C) {
    __shared__ __align__(16) float sA[2][32][68];   // [buf][k][r] transposed
    __shared__ __align__(16) float sB[2][32][68];   // [buf][k][c]

    const int tid  = threadIdx.x;
    const int rr   = (tid >> 4) * 8;
    const int cc   = (tid & 15) * 4;
    const int row0 = blockIdx.x * 64;
    const int col0 = blockIdx.y * 64;

    float acc[8][4];
#pragma unroll
    for (int i = 0; i < 8; i++)
#pragma unroll
        for (int j = 0; j < 4; j++) acc[i][j] = 0.f;

    // per-thread staging: A 4 chunks, B 4 chunks (float4 each)
    float4 va[4], vb[4];
    constexpr int NT = KD / 32;

    // --- prologue: load + store tile 0 ---
#pragma unroll
    for (int i = 0; i < 4; i++) {
        const int id = tid + i * 128;
        va[i] = *(const float4*)&A[(size_t)(row0 + (id >> 3)) * KD + (id & 7) * 4];
        vb[i] = *(const float4*)&B[(size_t)(id >> 4) * ND + col0 + (id & 15) * 4];
    }
#pragma unroll
    for (int i = 0; i < 4; i++) {
        const int id = tid + i * 128;
        const int r = id >> 3, c4 = (id & 7) * 4;
        sA[0][c4 + 0][r] = va[i].x;
        sA[0][c4 + 1][r] = va[i].y;
        sA[0][c4 + 2][r] = va[i].z;
        sA[0][c4 + 3][r] = va[i].w;
        *(float4*)&sB[0][id >> 4][(id & 15) * 4] = vb[i];
    }
    __syncthreads();

    for (int t = 0; t < NT; t++) {
        const int cur = t & 1;
        // issue global loads for next tile early
        if (t + 1 < NT) {
            const int k0 = (t + 1) * 32;
#pragma unroll
            for (int i = 0; i < 4; i++) {
                const int id = tid + i * 128;
                va[i] = *(const float4*)&A[(size_t)(row0 + (id >> 3)) * KD + k0 + (id & 7) * 4];
                vb[i] = *(const float4*)&B[(size_t)(k0 + (id >> 4)) * ND + col0 + (id & 15) * 4];
            }
        }
        // compute on current buffer
#pragma unroll
        for (int kk = 0; kk < 32; kk++) {
            const float4 b  = *(const float4*)&sB[cur][kk][cc];
            const float4 a0 = *(const float4*)&sA[cur][kk][rr];
            const float4 a1 = *(const float4*)&sA[cur][kk][rr + 4];
            acc[0][0] += a0.x * b.x; acc[0][1] += a0.x * b.y; acc[0][2] += a0.x * b.z; acc[0][3] += a0.x * b.w;
            acc[1][0] += a0.y * b.x; acc[1][1] += a0.y * b.y; acc[1][2] += a0.y * b.z; acc[1][3] += a0.y * b.w;
            acc[2][0] += a0.z * b.x; acc[2][1] += a0.z * b.y; acc[2][2] += a0.z * b.z; acc[2][3] += a0.z * b.w;
            acc[3][0] += a0.w * b.x; acc[3][1] += a0.w * b.y; acc[3][2] += a0.w * b.z; acc[3][3] += a0.w * b.w;
            acc[4][0] += a1.x * b.x; acc[4][1] += a1.x * b.y; acc[4][2] += a1.x * b.z; acc[4][3] += a1.x * b.w;
            acc[5][0] += a1.y * b.x; acc[5][1] += a1.y * b.y; acc[5][2] += a1.y * b.z; acc[5][3] += a1.y * b.w;
            acc[6][0] += a1.z * b.x; acc[6][1] += a1.z * b.y; acc[6][2] += a1.z * b.z; acc[6][3] += a1.z * b.w;
            acc[7][0] += a1.w * b.x; acc[7][1] += a1.w * b.y; acc[7][2] += a1.w * b.z; acc[7][3] += a1.w * b.w;
        }
        // store next tile and flip
        if (t + 1 < NT) {
            const int nxt = cur ^ 1;
#pragma unroll
            for (int i = 0; i < 4; i++) {
                const int id = tid + i * 128;
                const int r = id >> 3, c4 = (id & 7) * 4;
                sA[nxt][c4 + 0][r] = va[i].x;
                sA[nxt][c4 + 1][r] = va[i].y;
                sA[nxt][c4 + 2][r] = va[i].z;
                sA[nxt][c4 + 3][r] = va[i].w;
                *(float4*)&sB[nxt][id >> 4][(id & 15) * 4] = vb[i];
            }
            __syncthreads();
        }
    }

#pragma unroll
    for (int i = 0; i < 8; i++) {
        *(float4*)&C[(size_t)(row0 + rr + i) * ND + col0 + cc] =
            make_float4(acc[i][0], acc[i][1], acc[i][2], acc[i][3]);
    }
}

// ---------------- column stats (deterministic 2-stage) ----------------
template<int C>
__global__ __launch_bounds__(256)
void colstats(const float* __restrict__ y, float* __restrict__ part) {
    const int tid = threadIdx.x, bid = blockIdx.x;
    if (C == 256) {
        float s = 0.f, q = 0.f;
        for (int r = bid; r < NPTS; r += 256) {
            float v = y[(size_t)r * 256 + tid];
            s += v; q += v * v;
        }
        part[bid * 512 + tid] = s;
        part[bid * 512 + 256 + tid] = q;
    } else {
        const int c = tid & 63, rg = tid >> 6;
        float s = 0.f, q = 0.f;
        for (int r = bid * 4 + rg; r < NPTS; r += 1024) {
            float v = y[(size_t)r * 64 + c];
            s += v; q += v * v;
        }
        __shared__ float sh[2][256];
        sh[0][tid] = s; sh[1][tid] = q;
        __syncthreads();
        if (tid < 64) {
            s = sh[0][tid] + sh[0][tid + 64] + sh[0][tid + 128] + sh[0][tid + 192];
            q = sh[1][tid] + sh[1][tid + 64] + sh[1][tid + 128] + sh[1][tid + 192];
            part[bid * 128 + tid] = s;
            part[bid * 128 + 64 + tid] = q;
        }
    }
}

template<int C>
__global__ void finalize_bn(const float* __restrict__ part,
                            const float* __restrict__ g, const float* __restrict__ b,
                            float* __restrict__ bnout) {
    const int c = threadIdx.x;
    float s = 0.f, q = 0.f;
    for (int i = 0; i < 256; i++) {
        s += part[i * 2 * C + c];
        q += part[i * 2 * C + C + c];
    }
    const float mean = s / (float)NPTS;
    const float var = q / (float)NPTS - mean * mean;
    const float sc = g[c] * rsqrtf(var + EPS);
    bnout[c] = sc;
    bnout[C + c] = b[c] - mean * sc;
}

// ---------------- BN1 apply + leaky relu (in place) ----------------
__global__ __launch_bounds__(256)
void bn_act_64(float* __restrict__ x, const float* __restrict__ bn) {
    const size_t i = (size_t)blockIdx.x * 256 + threadIdx.x;
    float4 v = ((float4*)x)[i];
    const int c = (int)((i * 4) & 63);
    v.x = leaky(v.x * bn[c + 0] + bn[64 + c + 0]);
    v.y = leaky(v.y * bn[c + 1] + bn[64 + c + 1]);
    v.z = leaky(v.z * bn[c + 2] + bn[64 + c + 2]);
    v.w = leaky(v.w * bn[c + 3] + bn[64 + c + 3]);
    ((float4*)x)[i] = v;
}

// ---------------- KPConv: influence weights + fk accumulation ----------------
// 16 points/block, 256 threads. w stored padded [p][h][16] so phase-2 loads
// weights as 4x LDS.128; x1 gathers prefetched one h ahead.
__global__ __launch_bounds__(256)
void kpconv_kernel(const float* __restrict__ xyz, const int* __restrict__ nbr,
                   const float* __restrict__ kp) {
    __shared__ __align__(16) float s_w[16][H][16];   // float4-accessed: keep 16B aligned
    __shared__ __align__(16) float s_kp[KPTS * 3 + 1];
    __shared__ int   s_nbr[16][H];

    const int tid = threadIdx.x;
    const int n0 = blockIdx.x * 16;

    if (tid < KPTS * 3) s_kp[tid] = kp[tid];
    __syncthreads();

    // phase 1: 512 (p,h) tasks
    for (int t = tid; t < 512; t += 256) {
        const int p = t >> 5, h = t & 31;
        const int n = n0 + p;
        const int j = nbr[n * H + h];
        s_nbr[p][h] = j;
        const float dx = xyz[j * 3 + 0] - xyz[n * 3 + 0];
        const float dy = xyz[j * 3 + 1] - xyz[n * 3 + 1];
        const float dz = xyz[j * 3 + 2] - xyz[n * 3 + 2];
        float* wp = &s_w[p][h][0];
#pragma unroll
        for (int k = 0; k < KPTS; k++) {
            const float ex = dx - s_kp[k * 3 + 0];
            const float ey = dy - s_kp[k * 3 + 1];
            const float ez = dz - s_kp[k * 3 + 2];
            const float sq = ex * ex + ey * ey + ez * ez;
            wp[k] = fmaxf(1.f - sqrtf(sq) * (1.f / INFL), 0.f);
        }
        wp[15] = 0.f;
    }
    __syncthreads();

    // phase 2: 16 threads per point, each owns a float4 d-slice
    const int p = tid >> 4;
    const int d0 = (tid & 15) * 4;
    const int n = n0 + p;
    float acc[KPTS][4];
#pragma unroll
    for (int k = 0; k < KPTS; k++) {
        acc[k][0] = 0.f; acc[k][1] = 0.f; acc[k][2] = 0.f; acc[k][3] = 0.f;
    }

    int j = s_nbr[p][0];
    float4 v = *(const float4*)&g_x1[(size_t)j * 64 + d0];
    for (int h = 0; h < H; h++) {
        float4 vn;
        if (h + 1 < H) {
            const int jn = s_nbr[p][h + 1];
            vn = *(const float4*)&g_x1[(size_t)jn * 64 + d0];
        }
        const float4 w0 = *(const float4*)&s_w[p][h][0];
        const float4 w1 = *(const float4*)&s_w[p][h][4];
        const float4 w2 = *(const float4*)&s_w[p][h][8];
        const float4 w3 = *(const float4*)&s_w[p][h][12];
        const float wv[15] = {w0.x, w0.y, w0.z, w0.w, w1.x, w1.y, w1.z, w1.w,
                              w2.x, w2.y, w2.z, w2.w, w3.x, w3.y, w3.z};
#pragma unroll
        for (int k = 0; k < KPTS; k++) {
            const float w = wv[k];
            acc[k][0] += w * v.x; acc[k][1] += w * v.y;
            acc[k][2] += w * v.z; acc[k][3] += w * v.w;
        }
        v = vn;
    }

    float* dst = &g_fk[(size_t)n * (KPTS * 64) + d0];
#pragma unroll
    for (int k = 0; k < KPTS; k++) {
        *(float4*)&dst[k * 64] = make_float4(acc[k][0], acc[k][1], acc[k][2], acc[k][3]);
    }
}

// ---------------- final combine ----------------
__global__ __launch_bounds__(256)
void combine_kernel(const float* __restrict__ y2, float* __restrict__ out,
                    const float* __restrict__ bn2, const float* __restrict__ bnsc) {
    const size_t i = (size_t)blockIdx.x * 256 + threadIdx.x;
    const int c = (int)((i * 4) & 255);
    float4 a = ((const float4*)y2)[i];
    float4 s = ((float4*)out)[i];
    float4 r;
    r.x = leaky(a.x * bn2[c + 0] + bn2[256 + c + 0]) + (s.x * bnsc[c + 0] + bnsc[256 + c + 0]);
    r.y = leaky(a.y * bn2[c + 1] + bn2[256 + c + 1]) + (s.y * bnsc[c + 1] + bnsc[256 + c + 1]);
    r.z = leaky(a.z * bn2[c + 2] + bn2[256 + c + 2]) + (s.z * bnsc[c + 2] + bnsc[256 + c + 2]);
    r.w = leaky(a.w * bn2[c + 3] + bn2[256 + c + 3]) + (s.w * bnsc[c + 3] + bnsc[256 + c + 3]);
    ((float4*)out)[i] = r;
}

// ---------------- launcher ----------------
extern "C" void kernel_launch(void* const* d_in, const int* in_sizes, int n_in,
                              void* d_out, int out_size) {
    const float* feats = (const float*)d_in[0];
    const float* xyz   = (const float*)d_in[1];
    const int*   nbr   = (const int*)d_in[3];
    const float* W1    = (const float*)d_in[4];
    const float* g1    = (const float*)d_in[5];
    const float* b1    = (const float*)d_in[6];
    const float* kpp   = (const float*)d_in[7];
    const float* kpw   = (const float*)d_in[8];   // [15*64][64] natural layout
    const float* W2    = (const float*)d_in[9];
    const float* g2    = (const float*)d_in[10];
    const float* b2    = (const float*)d_in[11];
    const float* Wsc   = (const float*)d_in[12];
    const float* gsc   = (const float*)d_in[13];
    const float* bsc   = (const float*)d_in[14];
    float* out = (float*)d_out;

    void *px1, *pfk, *pxkp, *py2, *ppart, *pbn1, *pbn2, *pbnsc;
    cudaGetSymbolAddress(&px1, g_x1);
    cudaGetSymbolAddress(&pfk, g_fk);
    cudaGetSymbolAddress(&pxkp, g_xkp);
    cudaGetSymbolAddress(&py2, g_y2);
    cudaGetSymbolAddress(&ppart, g_part);
    cudaGetSymbolAddress(&pbn1, g_bn1);
    cudaGetSymbolAddress(&pbn2, g_bn2);
    cudaGetSymbolAddress(&pbnsc, g_bnsc);
    float *x1 = (float*)px1, *fk = (float*)pfk, *xkp = (float*)pxkp;
    float *y2 = (float*)py2, *part = (float*)ppart;
    float *bn1 = (float*)pbn1, *bn2 = (float*)pbn2, *bnsc = (float*)pbnsc;

    // 1) unary_1: x1 = feats @ W1  [N,64]
    gemm_k<128, 64><<<dim3(1250, 1), 128>>>(feats, W1, x1);
    // 2) BN1 + act
    colstats<64><<<256, 256>>>(x1, part);
    finalize_bn<64><<<1, 64>>>(part, g1, b1, bn1);
    bn_act_64<<<NPTS * 64 / 4 / 256, 256>>>(x1, bn1);
    // 3) KPConv -> fk [N, 960]
    kpconv_kernel<<<NPTS / 16, 256>>>(xyz, nbr, kpp);
    // 4) x_kp = fk @ kp_weights  [N,960]@[960,64]
    gemm_k<960, 64><<<dim3(1250, 1), 128>>>(fk, kpw, xkp);
    // 5) y2 = x_kp @ W2  [N,256]
    gemm_k<64, 256><<<dim3(1250, 4), 128>>>(xkp, W2, y2);
    colstats<256><<<256, 256>>>(y2, part);
    finalize_bn<256><<<1, 256>>>(part, g2, b2, bn2);
    // 6) shortcut -> out raw
    gemm_k<128, 256><<<dim3(1250, 4), 128>>>(feats, Wsc, out);
    colstats<256><<<256, 256>>>(out, part);
    finalize_bn<256><<<1, 256>>>(part, gsc, bsc, bnsc);
    // 7) combine
    combine_kernel<<<NPTS * 256 / 4 / 256, 256>>>(y2, out, bn2, bnsc);
}